// round 12
// baseline (speedup 1.0000x reference)
#include <cuda_runtime.h>
#include <math.h>

// Problem constants (fixed by dataset)
#define BDIM 128
#define TDIM 512
#define IDIM 4
#define HDIM 512
#define ODIM 3
#define NREGC 256          // round(H * 0.5)

// Decomposition: 16 M-groups x 16 CTAs; CTA = 32 cols, group = 8 batch rows.
// 256 CTAs total -> 2 per SM (occupancy-driven latency hiding).
#define GM 16
#define GN 16
#define GRID (GM * GN)     // 256 CTAs
#define NTHREADS 256       // 8 warps
#define MT (BDIM / GM)     // 8 rows per group

// Thread tile: warp = colgroup (4 cols), lane = k-chunk (16 k), 8 rows.
// A stage: 8 rows x 640 words (16-float k-slot padded to 20 words; lane stride
// 5 quads, gcd(5,8)=1 -> conflict-free LDS.128 within each 8-lane phase)
#define AROW_W 640
#define A_WORDS (MT * AROW_W)            // 5120
#define SLICE_ULL 34                     // 272B per-thread W slice (32 ull used + pad)
#define SMEM_BYTES (A_WORDS * 4 + NTHREADS * SLICE_ULL * 8)   // 20480 + 69632 = 90112

__device__ float g_th[2][BDIM * HDIM];   // tanh(h) double buffer (L2-resident)
__device__ unsigned g_flags[GRID];       // per-CTA epoch flags (monotonic)
__device__ float g_regpart[GRID];        // per-CTA regularizer partials

__device__ __forceinline__ float tanh_fast(float x)
{
    float ax = fabsf(x);
    float e  = __expf(2.0f * ax);
    float r  = 1.0f - __fdividef(2.0f, e + 1.0f);
    return copysignf(r, x);
}

__device__ __forceinline__ unsigned long long pack2(float lo, float hi)
{
    return (unsigned long long)__float_as_uint(lo)
         | ((unsigned long long)__float_as_uint(hi) << 32);
}
__device__ __forceinline__ float lo2(unsigned long long u) { return __uint_as_float((unsigned)u); }
__device__ __forceinline__ float hi2(unsigned long long u) { return __uint_as_float((unsigned)(u >> 32)); }

__device__ __forceinline__ void ffma2(unsigned long long& acc,
                                      unsigned long long a,
                                      unsigned long long w)
{
    asm("fma.rn.f32x2 %0, %1, %2, %0;" : "+l"(acc) : "l"(a), "l"(w));
}

// Release store / acquire load for the barrier flags (gpu scope)
__device__ __forceinline__ void st_release_gpu(unsigned* p, unsigned v)
{
    asm volatile("st.release.gpu.global.u32 [%0], %1;" :: "l"(p), "r"(v) : "memory");
}
__device__ __forceinline__ unsigned ld_acquire_gpu(const unsigned* p)
{
    unsigned v;
    asm volatile("ld.acquire.gpu.global.u32 %0, [%1];" : "=r"(v) : "l"(p) : "memory");
    return v;
}

__global__ __launch_bounds__(NTHREADS, 2)
void rnn_persistent_kernel(const float* __restrict__ x,      // (B,T,I)
                           const float* __restrict__ h0,     // (B,H)
                           const float* __restrict__ Wrec,   // (H,H)
                           const float* __restrict__ Win,    // (I,H)
                           const float* __restrict__ Wout,   // (H,O)
                           const float* __restrict__ brec,   // (H)
                           const float* __restrict__ bin,    // (H)
                           float* __restrict__ out)
{
    extern __shared__ __align__(16) float smem[];
    float* Asm = smem;                                   // [8][640] words
    unsigned long long* Wbase = (unsigned long long*)(smem + A_WORDS);

    __shared__ float s_red[NTHREADS / 32];
    __shared__ unsigned s_base;

    const int tid  = threadIdx.x;
    const int w    = tid >> 5;          // warp 0..7 == colgroup (4 cols)
    const int lane = tid & 31;          // == k-chunk (16 k each)
    const int bx   = blockIdx.x;
    const int gm   = bx / GN;           // M-group
    const int gn   = bx % GN;           // column-slice rank (32 cols)

    const int nbase = gn * 32 + w * 4;
    const int n     = nbase + (lane >> 3);     // owned column after reduction
    const int row   = gm * MT + (lane & 7);    // owned batch row after reduction

    float* out_y   = out;
    float* out_hs  = out + (size_t)BDIM * TDIM * ODIM;
    float* out_reg = out_hs + (size_t)(TDIM + 1) * BDIM * HDIM;

    if (tid == 0) s_base = *((volatile unsigned*)&g_flags[bx]);
    __syncthreads();
    const unsigned base = s_base;

    // ---- stage this thread's private W slice (4 cols x 16 k, packed k-pairs) ----
    unsigned long long* Wsl = Wbase + (size_t)tid * SLICE_ULL;
    #pragma unroll
    for (int u = 0; u < 32; ++u) {
        int kb = u >> 3, p = (u >> 2) & 1, c = u & 3;
        int k  = lane * 16 + kb * 4 + p * 2;
        Wsl[u] = pack2(Wrec[(size_t)k * HDIM + nbase + c],
                       Wrec[(size_t)(k + 1) * HDIM + nbase + c]);
    }
    const ulonglong2* Wsl2 = (const ulonglong2*)Wsl;

    // ---- persistent per-thread state (one element) ----
    const float4 win = { Win[0*HDIM + n], Win[1*HDIM + n], Win[2*HDIM + n], Win[3*HDIM + n] };
    const float bsum = brec[n] + bin[n];
    const bool  doreg = (n < NREGC);

    float h  = h0[(size_t)row * HDIM + n];
    float zp = 0.f, racc = 0.f;

    __stcg(&out_hs[(size_t)row * HDIM + n], h);
    __stcg(&g_th[0][row * HDIM + n], tanh_fast(h));

    unsigned barcnt = 0;
    auto group_barrier = [&](unsigned target) {
        __syncthreads();
        if (tid == 0) st_release_gpu(&g_flags[bx], target);   // orders prior stores via bar+release
        if (tid < GN) {
            while ((int)(ld_acquire_gpu(&g_flags[gm * GN + tid]) - target) < 0) { }
        }
        __syncthreads();
    };

    group_barrier(base + (++barcnt));

    const ulonglong2* A2 = (const ulonglong2*)Asm;

    // =========================== main recurrence ===========================
    for (int t = 0; t < TDIM; ++t) {
        float4 xv = __ldcg((const float4*)(x + ((size_t)row * TDIM + t) * IDIM));

        // stage tanh(h_prev) (16KB) into k-slot-padded layout: 4 float4 per thread
        {
            const float4* src = (const float4*)(g_th[t & 1] + (size_t)gm * MT * HDIM);
            #pragma unroll
            for (int e = 0; e < 4; ++e) {
                int q = tid * 4 + e;                      // float4 index 0..1023
                float4 val = __ldcg(&src[q]);
                int r   = q >> 7;                         // 128 float4 per row
                int kw  = (q & 127) * 4;                  // word within row
                *(float4*)&Asm[r * AROW_W + (kw >> 4) * 20 + (kw & 15)] = val;
            }
        }
        __syncthreads();

        // GEMM: acc[c*8+r] packed over k-parity; W private slice, A broadcast
        unsigned long long acc[32];
        #pragma unroll
        for (int i = 0; i < 32; ++i) acc[i] = 0ull;

        #pragma unroll
        for (int kb = 0; kb < 4; ++kb) {
            ulonglong2 wA = Wsl2[kb * 4 + 0];
            ulonglong2 wB = Wsl2[kb * 4 + 1];
            ulonglong2 wC = Wsl2[kb * 4 + 2];
            ulonglong2 wD = Wsl2[kb * 4 + 3];
            #pragma unroll
            for (int r = 0; r < MT; ++r) {
                ulonglong2 a = A2[r * 160 + lane * 5 + kb];
                ffma2(acc[0*8 + r], a.x, wA.x);
                ffma2(acc[1*8 + r], a.x, wA.y);
                ffma2(acc[2*8 + r], a.x, wB.x);
                ffma2(acc[3*8 + r], a.x, wB.y);
                ffma2(acc[0*8 + r], a.y, wC.x);
                ffma2(acc[1*8 + r], a.y, wC.y);
                ffma2(acc[2*8 + r], a.y, wD.x);
                ffma2(acc[3*8 + r], a.y, wD.y);
            }
        }

        float v[32];
        #pragma unroll
        for (int i = 0; i < 32; ++i) v[i] = lo2(acc[i]) + hi2(acc[i]);

        // 32-lane value-halving butterfly; lane g ends owning index g (= c*8+r)
        int cnt = 32;
        #pragma unroll
        for (int s = 16; s >= 1; s >>= 1) {
            const int half = cnt >> 1;
            const bool hi = (lane & s) != 0;
            #pragma unroll
            for (int j = 0; j < 16; ++j) {
                if (j < half) {
                    float send = hi ? v[j] : v[j + half];
                    float recv = __shfl_xor_sync(0xffffffffu, send, s);
                    float keep = hi ? v[j + half] : v[j];
                    v[j] = keep + recv;
                }
            }
            cnt = half;
        }

        float z = v[0] + bsum;
        z = fmaf(xv.x, win.x, z); z = fmaf(xv.y, win.y, z);
        z = fmaf(xv.z, win.z, z); z = fmaf(xv.w, win.w, z);

        float hn = 0.5f * (h + z);          // alpha = 0.5

        if (doreg) {
            float d = hn - h; racc = fmaf(d, d, racc);
            if (t > 0) { float e = z - zp; racc = fmaf(e, e, racc); }
        }

        __stcg(&g_th[(t + 1) & 1][row * HDIM + n], tanh_fast(hn));
        __stcg(&out_hs[(size_t)(t + 1) * BDIM * HDIM + (size_t)row * HDIM + n], hn);

        h = hn; zp = z;

        group_barrier(base + (++barcnt));
    }

    // ---- regularizer partial per CTA, then one-sided final flag ----
    {
        float r = racc;
        #pragma unroll
        for (int off = 16; off; off >>= 1) r += __shfl_xor_sync(0xffffffffu, r, off);
        if (lane == 0) s_red[w] = r;
        __syncthreads();
        if (tid == 0) {
            float s = 0.f;
            #pragma unroll
            for (int i = 0; i < NTHREADS / 32; ++i) s += s_red[i];
            *((volatile float*)&g_regpart[bx]) = s;
            st_release_gpu(&g_flags[bx], base + barcnt + 1);
        }
    }

    if (bx == 0) {
        const unsigned target = base + barcnt + 1;
        if (tid < GRID) {   // 256 threads poll 256 flags
            while ((int)(ld_acquire_gpu(&g_flags[tid]) - target) < 0) { }
        }
        __syncthreads();
        if (tid == 0) {
            float s = 0.f;
            for (int i = 0; i < GRID; ++i)
                s += *((volatile float*)&g_regpart[i]);
            *out_reg = s / ((float)TDIM * (float)BDIM * (float)NREGC);
        }
    }

    // ---- outputs epilogue: out[b,t] = hs[t+1,b] @ W_out (group's 8 rows) ----
    __syncthreads();
    float* WoutS = Asm;   // reuse A stage: [512][4]
    for (int kk = tid; kk < HDIM; kk += NTHREADS) {
        WoutS[kk * 4 + 0] = Wout[kk * 3 + 0];
        WoutS[kk * 4 + 1] = Wout[kk * 3 + 1];
        WoutS[kk * 4 + 2] = Wout[kk * 3 + 2];
        WoutS[kk * 4 + 3] = 0.f;
    }
    __syncthreads();

    // 4096 items per group / 16 CTAs / 8 warps = 32 per warp
    for (int i = 0; i < 32; ++i) {
        int p  = (gn * (NTHREADS / 32) + w) * 32 + i;    // 0..4095 within group
        int tt = p >> 3;
        int bb = gm * MT + (p & 7);
        const float* hrow = out_hs + (size_t)(tt + 1) * BDIM * HDIM + (size_t)bb * HDIM;
        float o0 = 0.f, o1 = 0.f, o2 = 0.f;
        #pragma unroll 4
        for (int k = lane; k < HDIM; k += 32) {
            float  hv = __ldcg(&hrow[k]);
            float4 wv = ((const float4*)WoutS)[k];
            o0 = fmaf(hv, wv.x, o0);
            o1 = fmaf(hv, wv.y, o1);
            o2 = fmaf(hv, wv.z, o2);
        }
        #pragma unroll
        for (int off = 16; off; off >>= 1) {
            o0 += __shfl_xor_sync(0xffffffffu, o0, off);
            o1 += __shfl_xor_sync(0xffffffffu, o1, off);
            o2 += __shfl_xor_sync(0xffffffffu, o2, off);
        }
        if (lane == 0) {
            float* dst = out_y + ((size_t)bb * TDIM + tt) * ODIM;
            dst[0] = o0; dst[1] = o1; dst[2] = o2;
        }
    }
}

extern "C" void kernel_launch(void* const* d_in, const int* in_sizes, int n_in,
                              void* d_out, int out_size)
{
    (void)in_sizes; (void)n_in; (void)out_size;
    const float* x    = (const float*)d_in[0];
    const float* h0   = (const float*)d_in[1];
    const float* Wrec = (const float*)d_in[2];
    const float* Win  = (const float*)d_in[3];
    const float* Wout = (const float*)d_in[4];
    const float* brec = (const float*)d_in[5];
    const float* bin  = (const float*)d_in[6];
    float* out = (float*)d_out;

    cudaFuncSetAttribute(rnn_persistent_kernel,
                         cudaFuncAttributeMaxDynamicSharedMemorySize, SMEM_BYTES);

    rnn_persistent_kernel<<<GRID, NTHREADS, SMEM_BYTES>>>(
        x, h0, Wrec, Win, Wout, brec, bin, out);
}